// round 1
// baseline (speedup 1.0000x reference)
#include <cuda_runtime.h>

#define NH 64
#define IN_NODE 128
#define IN_EDGE 32
#define N_MAX 100000
#define E_MAX 1600000

// Scratch (static __device__ arrays; no allocation allowed)
__device__ float d_A[N_MAX * NH];     // h ping
__device__ float d_B[N_MAX * NH];     // h pong / P
__device__ float d_G[N_MAX * NH];     // agg scratch / Q
__device__ float d_inv[N_MAX];        // degree -> 1/max(cnt,1)
__device__ float d_Wec[IN_EDGE * NH]; // We @ W1c folded
__device__ float d_b1p[NH];           // b1 + be @ W1c
__device__ float d_w2s[NH];           // W2 @ Ws
__device__ float d_c2[1];             // b2 . Ws + bs

// ---------------------------------------------------------------------------
// Fold weight products (tiny, one block)
// ---------------------------------------------------------------------------
__global__ void fold_kernel(const float* __restrict__ W1, const float* __restrict__ b1,
                            const float* __restrict__ We, const float* __restrict__ be,
                            const float* __restrict__ W2, const float* __restrict__ b2,
                            const float* __restrict__ Ws, const float* __restrict__ bs) {
    int t = threadIdx.x;
    // Wec[k][j] = sum_m We[k][m] * W1[128+m][j]
    for (int idx = t; idx < IN_EDGE * NH; idx += blockDim.x) {
        int k = idx >> 6, j = idx & 63;
        float s = 0.f;
        for (int m = 0; m < NH; m++)
            s += We[k * NH + m] * W1[(128 + m) * NH + j];
        d_Wec[idx] = s;
    }
    if (t < NH) {
        float s = b1[t];
        for (int m = 0; m < NH; m++)
            s += be[m] * W1[(128 + m) * NH + t];
        d_b1p[t] = s;
        float w = 0.f;
        for (int k = 0; k < NH; k++)
            w += W2[t * NH + k] * Ws[k];
        d_w2s[t] = w;
    }
    if (t == 0) {
        float c = bs[0];
        for (int k = 0; k < NH; k++) c += b2[k] * Ws[k];
        d_c2[0] = c;
    }
}

// ---------------------------------------------------------------------------
// Node encoder: h = relu(x @ Wn + bn).  Warp per node, W in smem.
// ---------------------------------------------------------------------------
__global__ __launch_bounds__(256) void node_enc_kernel(
    const float* __restrict__ x, const float* __restrict__ Wn,
    const float* __restrict__ bn, float* __restrict__ out, int n) {
    __shared__ float sW[IN_NODE * NH];  // 32KB
    __shared__ float sX[8][IN_NODE];
    for (int i = threadIdx.x; i < IN_NODE * NH; i += 256) sW[i] = Wn[i];
    __syncthreads();
    int warp = threadIdx.x >> 5, lane = threadIdx.x & 31;
    int node = blockIdx.x * 8 + warp;
    if (node >= n) return;
    float b0 = bn[lane], b1v = bn[lane + 32];
#pragma unroll
    for (int c = 0; c < 4; c++)
        sX[warp][lane + c * 32] = x[(size_t)node * IN_NODE + lane + c * 32];
    __syncwarp();
    float z0 = b0, z1 = b1v;
#pragma unroll 8
    for (int k = 0; k < IN_NODE; k++) {
        float xv = sX[warp][k];
        z0 = fmaf(xv, sW[k * NH + lane], z0);
        z1 = fmaf(xv, sW[k * NH + lane + 32], z1);
    }
    out[(size_t)node * NH + lane] = fmaxf(z0, 0.f);
    out[(size_t)node * NH + lane + 32] = fmaxf(z1, 0.f);
}

// ---------------------------------------------------------------------------
// Degree count / inverse
// ---------------------------------------------------------------------------
__global__ void zero_kernel(float* __restrict__ p, int n) {
    int i = blockIdx.x * blockDim.x + threadIdx.x;
    if (i < n) p[i] = 0.f;
}

__global__ void count_kernel(const int* __restrict__ dst, float* __restrict__ cnt, int e) {
    int i = blockIdx.x * blockDim.x + threadIdx.x;
    if (i < e) atomicAdd(&cnt[dst[i]], 1.0f);
}

__global__ void inv_kernel(float* __restrict__ inv, int n) {
    int i = blockIdx.x * blockDim.x + threadIdx.x;
    if (i < n) inv[i] = 1.0f / fmaxf(inv[i], 1.0f);
}

// ---------------------------------------------------------------------------
// Scatter: agg[dst] += h[src].  Warp per edge (coalesced row access).
// ---------------------------------------------------------------------------
__global__ __launch_bounds__(256) void scatter_kernel(
    const int* __restrict__ src, const int* __restrict__ dst,
    const float* __restrict__ h, float* __restrict__ agg, int e) {
    int gw = (blockIdx.x * 256 + threadIdx.x) >> 5;
    int lane = threadIdx.x & 31;
    if (gw >= e) return;
    int s = __ldg(&src[gw]), d = __ldg(&dst[gw]);
    float v0 = h[(size_t)s * NH + lane];
    float v1 = h[(size_t)s * NH + lane + 32];
    atomicAdd(&agg[(size_t)d * NH + lane], v0);
    atomicAdd(&agg[(size_t)d * NH + lane + 32], v1);
}

// ---------------------------------------------------------------------------
// SAGE combine: h_out = relu((agg*inv) @ Wl + bl + h @ Wr). Warp per node.
// ---------------------------------------------------------------------------
__global__ __launch_bounds__(256) void combine_kernel(
    const float* __restrict__ hin, const float* __restrict__ agg,
    const float* __restrict__ inv,
    const float* __restrict__ Wl, const float* __restrict__ bl,
    const float* __restrict__ Wr, float* __restrict__ hout, int n) {
    __shared__ float sWl[NH * NH];  // 16KB
    __shared__ float sWr[NH * NH];  // 16KB
    __shared__ float sRow[8][2 * NH];
    for (int i = threadIdx.x; i < NH * NH; i += 256) {
        sWl[i] = Wl[i];
        sWr[i] = Wr[i];
    }
    __syncthreads();
    int warp = threadIdx.x >> 5, lane = threadIdx.x & 31;
    int node = blockIdx.x * 8 + warp;
    if (node >= n) return;
    float iv = inv[node];
    sRow[warp][lane]        = agg[(size_t)node * NH + lane] * iv;
    sRow[warp][lane + 32]   = agg[(size_t)node * NH + lane + 32] * iv;
    sRow[warp][64 + lane]   = hin[(size_t)node * NH + lane];
    sRow[warp][96 + lane]   = hin[(size_t)node * NH + lane + 32];
    __syncwarp();
    float z0 = bl[lane], z1 = bl[lane + 32];
#pragma unroll 8
    for (int k = 0; k < NH; k++) {
        float av = sRow[warp][k];
        float hv = sRow[warp][64 + k];
        z0 = fmaf(av, sWl[k * NH + lane], z0);
        z0 = fmaf(hv, sWr[k * NH + lane], z0);
        z1 = fmaf(av, sWl[k * NH + lane + 32], z1);
        z1 = fmaf(hv, sWr[k * NH + lane + 32], z1);
    }
    hout[(size_t)node * NH + lane] = fmaxf(z0, 0.f);
    hout[(size_t)node * NH + lane + 32] = fmaxf(z1, 0.f);
}

// ---------------------------------------------------------------------------
// P = h @ W1[0:64], Q = h @ W1[64:128].  Warp per node.
// ---------------------------------------------------------------------------
__global__ __launch_bounds__(256) void pq_kernel(
    const float* __restrict__ h, const float* __restrict__ W1,
    float* __restrict__ P, float* __restrict__ Q, int n) {
    __shared__ float sWa[NH * NH];
    __shared__ float sWb[NH * NH];
    __shared__ float sRow[8][NH];
    for (int i = threadIdx.x; i < NH * NH; i += 256) {
        sWa[i] = W1[i];
        sWb[i] = W1[NH * NH + i];
    }
    __syncthreads();
    int warp = threadIdx.x >> 5, lane = threadIdx.x & 31;
    int node = blockIdx.x * 8 + warp;
    if (node >= n) return;
    sRow[warp][lane]      = h[(size_t)node * NH + lane];
    sRow[warp][lane + 32] = h[(size_t)node * NH + lane + 32];
    __syncwarp();
    float p0 = 0.f, p1 = 0.f, q0 = 0.f, q1 = 0.f;
#pragma unroll 8
    for (int k = 0; k < NH; k++) {
        float hv = sRow[warp][k];
        p0 = fmaf(hv, sWa[k * NH + lane], p0);
        p1 = fmaf(hv, sWa[k * NH + lane + 32], p1);
        q0 = fmaf(hv, sWb[k * NH + lane], q0);
        q1 = fmaf(hv, sWb[k * NH + lane + 32], q1);
    }
    P[(size_t)node * NH + lane]      = p0;
    P[(size_t)node * NH + lane + 32] = p1;
    Q[(size_t)node * NH + lane]      = q0;
    Q[(size_t)node * NH + lane + 32] = q1;
}

// ---------------------------------------------------------------------------
// Edge kernel: out[e] = relu(P[src]+Q[dst]+ea@Wec+b1') . w2s + c2
// Block = 128 edges, warp per edge (16 edges/warp). Wec columns in registers.
// ---------------------------------------------------------------------------
__global__ __launch_bounds__(256) void edge_kernel(
    const int* __restrict__ src, const int* __restrict__ dst,
    const float* __restrict__ ea, const float* __restrict__ P,
    const float* __restrict__ Q, float* __restrict__ out, int e) {
    __shared__ float sEA[128 * IN_EDGE];  // 16KB
    int warp = threadIdx.x >> 5, lane = threadIdx.x & 31;

    float wc0[IN_EDGE], wc1[IN_EDGE];
#pragma unroll
    for (int k = 0; k < IN_EDGE; k++) {
        wc0[k] = d_Wec[k * NH + lane];
        wc1[k] = d_Wec[k * NH + lane + 32];
    }
    float b0 = d_b1p[lane], b1v = d_b1p[lane + 32];
    float ws0 = d_w2s[lane], ws1 = d_w2s[lane + 32];
    float c2 = d_c2[0];

    int base = blockIdx.x * 128;
    int cnt = min(128, e - base);

    // coalesced tile load of edge_attr
    const float4* eag = (const float4*)(ea + (size_t)base * IN_EDGE);
    float4* eas = (float4*)sEA;
    int n4 = cnt * (IN_EDGE / 4);
    for (int i = threadIdx.x; i < n4; i += 256) eas[i] = eag[i];
    __syncthreads();

    for (int el = warp; el < cnt; el += 8) {
        int eg = base + el;
        int s = __ldg(&src[eg]), d = __ldg(&dst[eg]);
        float z0 = b0 + P[(size_t)s * NH + lane] + Q[(size_t)d * NH + lane];
        float z1 = b1v + P[(size_t)s * NH + lane + 32] + Q[(size_t)d * NH + lane + 32];
        const float* row = sEA + el * IN_EDGE;
#pragma unroll
        for (int k = 0; k < IN_EDGE; k++) {
            float a = row[k];
            z0 = fmaf(a, wc0[k], z0);
            z1 = fmaf(a, wc1[k], z1);
        }
        float v = fmaxf(z0, 0.f) * ws0 + fmaxf(z1, 0.f) * ws1;
#pragma unroll
        for (int off = 16; off; off >>= 1)
            v += __shfl_down_sync(0xffffffffu, v, off);
        if (lane == 0) out[eg] = v + c2;
    }
}

// ---------------------------------------------------------------------------
// Launch
// ---------------------------------------------------------------------------
extern "C" void kernel_launch(void* const* d_in, const int* in_sizes, int n_in,
                              void* d_out, int out_size) {
    const float* x    = (const float*)d_in[0];
    const int* eidx   = (const int*)d_in[1];
    const float* ea   = (const float*)d_in[2];
    const float* Wn   = (const float*)d_in[3];
    const float* bn   = (const float*)d_in[4];
    const float* We   = (const float*)d_in[5];
    const float* be   = (const float*)d_in[6];
    const float* Wl0  = (const float*)d_in[7];
    const float* bl0  = (const float*)d_in[8];
    const float* Wr0  = (const float*)d_in[9];
    const float* Wl1  = (const float*)d_in[10];
    const float* bl1  = (const float*)d_in[11];
    const float* Wr1  = (const float*)d_in[12];
    const float* W1   = (const float*)d_in[13];
    const float* b1   = (const float*)d_in[14];
    const float* W2   = (const float*)d_in[15];
    const float* b2   = (const float*)d_in[16];
    const float* Ws   = (const float*)d_in[17];
    const float* bs   = (const float*)d_in[18];
    float* out = (float*)d_out;

    int n = in_sizes[0] / IN_NODE;
    int e = in_sizes[2] / IN_EDGE;
    const int* src = eidx;
    const int* dst = eidx + e;

    float *A, *B, *G, *inv;
    cudaGetSymbolAddress((void**)&A, d_A);
    cudaGetSymbolAddress((void**)&B, d_B);
    cudaGetSymbolAddress((void**)&G, d_G);
    cudaGetSymbolAddress((void**)&inv, d_inv);

    int nb_node = (n + 7) / 8;          // warp per node, 8 warps/block
    int nb_nvec = (n * NH + 255) / 256; // element-wise over [N,64]
    int nb_n = (n + 255) / 256;
    int nb_e = (e + 255) / 256;
    int nb_sc = ((e * 32) + 255) / 256; // warp per edge
    int nb_ed = (e + 127) / 128;

    // weight folding
    fold_kernel<<<1, 256>>>(W1, b1, We, be, W2, b2, Ws, bs);

    // node encoder -> A
    node_enc_kernel<<<nb_node, 256>>>(x, Wn, bn, A, n);

    // degree + inverse (reuse inv as cnt)
    zero_kernel<<<nb_n, 256>>>(inv, n);
    count_kernel<<<nb_e, 256>>>(dst, inv, e);
    inv_kernel<<<nb_n, 256>>>(inv, n);

    // SAGE layer 0: A -> B
    zero_kernel<<<nb_nvec, 256>>>(G, n * NH);
    scatter_kernel<<<nb_sc, 256>>>(src, dst, A, G, e);
    combine_kernel<<<nb_node, 256>>>(A, G, inv, Wl0, bl0, Wr0, B, n);

    // SAGE layer 1: B -> A
    zero_kernel<<<nb_nvec, 256>>>(G, n * NH);
    scatter_kernel<<<nb_sc, 256>>>(src, dst, B, G, e);
    combine_kernel<<<nb_node, 256>>>(B, G, inv, Wl1, bl1, Wr1, A, n);

    // P = A @ W1a -> B, Q = A @ W1b -> G
    pq_kernel<<<nb_node, 256>>>(A, W1, B, G, n);

    // edge output
    edge_kernel<<<nb_ed, 256>>>(src, dst, ea, B, G, out, e);
}